// round 1
// baseline (speedup 1.0000x reference)
#include <cuda_runtime.h>
#include <cuda_bf16.h>
#include <math_constants.h>

// Problem constants
#define NSEQ 4096
#define DIN  1024
#define HID  512

// Scratch (allocation-free rule: __device__ globals)
__device__ float g_Q[NSEQ * HID];
__device__ float g_K[NSEQ * HID];
__device__ float g_V[NSEQ * HID];
__device__ float g_S[(size_t)NSEQ * NSEQ];   // 64 MB

// ---------------------------------------------------------------------------
// Tiled GEMM, C[M,N] = A[M,K] * B^T  (B is [N,K] row-major), optional bias[N].
// BM=BN=128, BK=16, 256 threads, 8x8 register tile per thread.
// All dims are multiples of the tiles -> no bounds checks.
// ---------------------------------------------------------------------------
#define BM 128
#define BN 128
#define BK 16
#define TM 8
#define TN 8

__global__ __launch_bounds__(256) void gemm_nt(
    const float* __restrict__ A, const float* __restrict__ B,
    const float* __restrict__ bias, float* __restrict__ C,
    int M, int Nn, int K)
{
    __shared__ float As[BK][BM];
    __shared__ float Bs[BK][BN];

    const int tid = threadIdx.x;
    const int bm = blockIdx.y * BM;
    const int bn = blockIdx.x * BN;

    const int tx = tid & 15;   // N direction (16)
    const int ty = tid >> 4;   // M direction (16)

    // global-load indexing: 64 rows x 4 float4-cols per pass, 2 passes
    const int lr = tid >> 2;          // 0..63
    const int lc = (tid & 3) * 4;     // 0,4,8,12

    float acc[TM][TN];
    #pragma unroll
    for (int i = 0; i < TM; i++)
        #pragma unroll
        for (int j = 0; j < TN; j++) acc[i][j] = 0.0f;

    for (int k0 = 0; k0 < K; k0 += BK) {
        #pragma unroll
        for (int r = 0; r < 2; r++) {
            int row = lr + r * 64;
            float4 va = *(const float4*)(A + (size_t)(bm + row) * K + k0 + lc);
            As[lc + 0][row] = va.x; As[lc + 1][row] = va.y;
            As[lc + 2][row] = va.z; As[lc + 3][row] = va.w;
            float4 vb = *(const float4*)(B + (size_t)(bn + row) * K + k0 + lc);
            Bs[lc + 0][row] = vb.x; Bs[lc + 1][row] = vb.y;
            Bs[lc + 2][row] = vb.z; Bs[lc + 3][row] = vb.w;
        }
        __syncthreads();

        #pragma unroll
        for (int k = 0; k < BK; k++) {
            float ra[TM], rb[TN];
            #pragma unroll
            for (int i = 0; i < TM; i++) ra[i] = As[k][ty * TM + i];
            #pragma unroll
            for (int j = 0; j < TN; j++) rb[j] = Bs[k][tx * TN + j];
            #pragma unroll
            for (int i = 0; i < TM; i++)
                #pragma unroll
                for (int j = 0; j < TN; j++)
                    acc[i][j] = fmaf(ra[i], rb[j], acc[i][j]);
        }
        __syncthreads();
    }

    #pragma unroll
    for (int i = 0; i < TM; i++) {
        int row = bm + ty * TM + i;
        #pragma unroll
        for (int j = 0; j < TN; j += 4) {
            int col = bn + tx * TN + j;
            float4 v;
            v.x = acc[i][j + 0]; v.y = acc[i][j + 1];
            v.z = acc[i][j + 2]; v.w = acc[i][j + 3];
            if (bias) {
                v.x += bias[col + 0]; v.y += bias[col + 1];
                v.z += bias[col + 2]; v.w += bias[col + 3];
            }
            *(float4*)(C + (size_t)row * Nn + col) = v;
        }
    }
}

// ---------------------------------------------------------------------------
// Tiled GEMM NN: C[M,N] = A[M,K] * B[K,N]  (B row-major, N contiguous).
// ---------------------------------------------------------------------------
__global__ __launch_bounds__(256) void gemm_nn(
    const float* __restrict__ A, const float* __restrict__ B,
    float* __restrict__ C, int M, int Nn, int K)
{
    __shared__ float As[BK][BM];
    __shared__ float Bs[BK][BN];

    const int tid = threadIdx.x;
    const int bm = blockIdx.y * BM;
    const int bn = blockIdx.x * BN;

    const int tx = tid & 15;
    const int ty = tid >> 4;

    const int lr = tid >> 2;          // A load: 0..63
    const int lc = (tid & 3) * 4;
    const int lrB = tid >> 5;         // B load: 0..7
    const int lcB = (tid & 31) * 4;   // 0..124

    float acc[TM][TN];
    #pragma unroll
    for (int i = 0; i < TM; i++)
        #pragma unroll
        for (int j = 0; j < TN; j++) acc[i][j] = 0.0f;

    for (int k0 = 0; k0 < K; k0 += BK) {
        #pragma unroll
        for (int r = 0; r < 2; r++) {
            int row = lr + r * 64;
            float4 va = *(const float4*)(A + (size_t)(bm + row) * K + k0 + lc);
            As[lc + 0][row] = va.x; As[lc + 1][row] = va.y;
            As[lc + 2][row] = va.z; As[lc + 3][row] = va.w;
        }
        #pragma unroll
        for (int r = 0; r < 2; r++) {
            int row = lrB + r * 8;
            float4 vb = *(const float4*)(B + (size_t)(k0 + row) * Nn + bn + lcB);
            *(float4*)&Bs[row][lcB] = vb;
        }
        __syncthreads();

        #pragma unroll
        for (int k = 0; k < BK; k++) {
            float ra[TM], rb[TN];
            #pragma unroll
            for (int i = 0; i < TM; i++) ra[i] = As[k][ty * TM + i];
            #pragma unroll
            for (int j = 0; j < TN; j++) rb[j] = Bs[k][tx * TN + j];
            #pragma unroll
            for (int i = 0; i < TM; i++)
                #pragma unroll
                for (int j = 0; j < TN; j++)
                    acc[i][j] = fmaf(ra[i], rb[j], acc[i][j]);
        }
        __syncthreads();
    }

    #pragma unroll
    for (int i = 0; i < TM; i++) {
        int row = bm + ty * TM + i;
        #pragma unroll
        for (int j = 0; j < TN; j += 4) {
            int col = bn + tx * TN + j;
            float4 v;
            v.x = acc[i][j + 0]; v.y = acc[i][j + 1];
            v.z = acc[i][j + 2]; v.w = acc[i][j + 3];
            *(float4*)(C + (size_t)row * Nn + col) = v;
        }
    }
}

// ---------------------------------------------------------------------------
// Row softmax over 4096 columns. One block (256 threads) per row.
// Row cached in shared memory; two block reductions (max, sum).
// ---------------------------------------------------------------------------
__global__ __launch_bounds__(256) void softmax_rows(float* __restrict__ S)
{
    __shared__ float buf[NSEQ];
    __shared__ float red[8];

    const int tid = threadIdx.x;
    const int lane = tid & 31;
    const int warp = tid >> 5;
    float* p = S + (size_t)blockIdx.x * NSEQ;

    // pass 1: load + max
    float m = -CUDART_INF_F;
    for (int i = tid * 4; i < NSEQ; i += 256 * 4) {
        float4 v = *(const float4*)(p + i);
        *(float4*)&buf[i] = v;
        m = fmaxf(m, fmaxf(fmaxf(v.x, v.y), fmaxf(v.z, v.w)));
    }
    #pragma unroll
    for (int o = 16; o > 0; o >>= 1) m = fmaxf(m, __shfl_xor_sync(0xffffffffu, m, o));
    if (lane == 0) red[warp] = m;
    __syncthreads();
    if (warp == 0) {
        float v = (lane < 8) ? red[lane] : -CUDART_INF_F;
        #pragma unroll
        for (int o = 4; o > 0; o >>= 1) v = fmaxf(v, __shfl_xor_sync(0xffffffffu, v, o));
        if (lane == 0) red[0] = v;
    }
    __syncthreads();
    m = red[0];
    __syncthreads();

    // pass 2: exp + sum
    float s = 0.0f;
    for (int i = tid * 4; i < NSEQ; i += 256 * 4) {
        float4 v = *(const float4*)&buf[i];
        v.x = __expf(v.x - m); v.y = __expf(v.y - m);
        v.z = __expf(v.z - m); v.w = __expf(v.w - m);
        *(float4*)&buf[i] = v;
        s += v.x + v.y + v.z + v.w;
    }
    #pragma unroll
    for (int o = 16; o > 0; o >>= 1) s += __shfl_xor_sync(0xffffffffu, s, o);
    if (lane == 0) red[warp] = s;
    __syncthreads();
    if (warp == 0) {
        float v = (lane < 8) ? red[lane] : 0.0f;
        #pragma unroll
        for (int o = 4; o > 0; o >>= 1) v += __shfl_xor_sync(0xffffffffu, v, o);
        if (lane == 0) red[0] = v;
    }
    __syncthreads();
    const float inv = 1.0f / red[0];

    // pass 3: normalize + store
    for (int i = tid * 4; i < NSEQ; i += 256 * 4) {
        float4 v = *(const float4*)&buf[i];
        v.x *= inv; v.y *= inv; v.z *= inv; v.w *= inv;
        *(float4*)(p + i) = v;
    }
}

// ---------------------------------------------------------------------------
// Launch
// ---------------------------------------------------------------------------
extern "C" void kernel_launch(void* const* d_in, const int* in_sizes, int n_in,
                              void* d_out, int out_size)
{
    const float* embs = (const float*)d_in[0];
    const float* Wq   = (const float*)d_in[1];
    const float* bq   = (const float*)d_in[2];
    const float* Wk   = (const float*)d_in[3];
    const float* bk   = (const float*)d_in[4];
    const float* Wv   = (const float*)d_in[5];
    const float* bv   = (const float*)d_in[6];
    float* out = (float*)d_out;

    float *Q, *K, *V, *S;
    cudaGetSymbolAddress((void**)&Q, g_Q);
    cudaGetSymbolAddress((void**)&K, g_K);
    cudaGetSymbolAddress((void**)&V, g_V);
    cudaGetSymbolAddress((void**)&S, g_S);

    dim3 blk(256);

    // Q/K/V projections: [4096,1024] x [512,1024]^T + bias
    dim3 gProj(HID / BN, NSEQ / BM);      // (4, 32)
    gemm_nt<<<gProj, blk>>>(embs, Wq, bq, Q, NSEQ, HID, DIN);
    gemm_nt<<<gProj, blk>>>(embs, Wk, bk, K, NSEQ, HID, DIN);
    gemm_nt<<<gProj, blk>>>(embs, Wv, bv, V, NSEQ, HID, DIN);

    // S = Q * K^T : [4096,512] x [4096,512]^T
    dim3 gS(NSEQ / BN, NSEQ / BM);        // (32, 32)
    gemm_nt<<<gS, blk>>>(Q, K, nullptr, S, NSEQ, NSEQ, HID);

    // row softmax
    softmax_rows<<<NSEQ, blk>>>(S);

    // out = P * V : [4096,4096] x [4096,512]
    dim3 gO(HID / BN, NSEQ / BM);         // (4, 32)
    gemm_nn<<<gO, blk>>>(S, V, out, NSEQ, HID, NSEQ);
}

// round 3
// speedup vs baseline: 2.6505x; 2.6505x over previous
#include <cuda_runtime.h>
#include <cuda_bf16.h>
#include <math_constants.h>
#include <cstdint>

#define NSEQ 4096
#define DIN  1024
#define HID  512

// ---------------------------------------------------------------------------
// Device scratch (allocation-free rules)
// ---------------------------------------------------------------------------
__device__ float g_Q [(size_t)NSEQ * HID];
__device__ float g_K [(size_t)NSEQ * HID];
__device__ float g_Vt[(size_t)HID  * NSEQ];
__device__ float g_S [(size_t)NSEQ * NSEQ];                 // 64 MB

__device__ __nv_bfloat16 g_ea [(size_t)NSEQ * 3 * DIN];    // embs A-form
__device__ __nv_bfloat16 g_eb [(size_t)NSEQ * 3 * DIN];    // embs B-form
__device__ __nv_bfloat16 g_Wqb[(size_t)HID  * 3 * DIN];
__device__ __nv_bfloat16 g_Wkb[(size_t)HID  * 3 * DIN];
__device__ __nv_bfloat16 g_Wva[(size_t)HID  * 3 * DIN];
__device__ __nv_bfloat16 g_Qa [(size_t)NSEQ * 3 * HID];
__device__ __nv_bfloat16 g_Kb [(size_t)NSEQ * 3 * HID];
__device__ __nv_bfloat16 g_Sa [(size_t)NSEQ * 3 * NSEQ];   // 96 MB
__device__ __nv_bfloat16 g_Vtb[(size_t)HID  * 3 * NSEQ];

// ---------------------------------------------------------------------------
// Split conversion: X[M,K] fp32 -> Y[M,3K] bf16.
//   A-side: [hi | hi | lo]     B-side: [hi | lo | hi]
// so that A' @ B'^T over 3K = Ah*Bh + Ah*Bl + Al*Bh.
// ---------------------------------------------------------------------------
__global__ __launch_bounds__(256) void split3_kernel(
    const float* __restrict__ X, __nv_bfloat16* __restrict__ Y,
    int K, int total4, int bside)
{
    int i = blockIdx.x * blockDim.x + threadIdx.x;
    if (i >= total4) return;
    int e = i * 4;
    int row = e / K;
    int col = e - row * K;

    float4 v = *(const float4*)(X + e);
    __nv_bfloat16 h0 = __float2bfloat16_rn(v.x);
    __nv_bfloat16 h1 = __float2bfloat16_rn(v.y);
    __nv_bfloat16 h2 = __float2bfloat16_rn(v.z);
    __nv_bfloat16 h3 = __float2bfloat16_rn(v.w);
    __nv_bfloat16 l0 = __float2bfloat16_rn(v.x - __bfloat162float(h0));
    __nv_bfloat16 l1 = __float2bfloat16_rn(v.y - __bfloat162float(h1));
    __nv_bfloat16 l2 = __float2bfloat16_rn(v.z - __bfloat162float(h2));
    __nv_bfloat16 l3 = __float2bfloat16_rn(v.w - __bfloat162float(h3));

    ushort4 ph = make_ushort4(__bfloat16_as_ushort(h0), __bfloat16_as_ushort(h1),
                              __bfloat16_as_ushort(h2), __bfloat16_as_ushort(h3));
    ushort4 pl = make_ushort4(__bfloat16_as_ushort(l0), __bfloat16_as_ushort(l1),
                              __bfloat16_as_ushort(l2), __bfloat16_as_ushort(l3));

    size_t base = (size_t)row * (3 * (size_t)K);
    int hi2 = bside ? 2 * K : K;     // second hi segment
    int lo1 = bside ? K : 2 * K;     // lo segment
    *(ushort4*)(Y + base + col)        = ph;
    *(ushort4*)(Y + base + hi2 + col)  = ph;
    *(ushort4*)(Y + base + lo1 + col)  = pl;
}

// ---------------------------------------------------------------------------
// bf16 NT GEMM via mma.sync: C[M,N] = A[M,Kg] @ B[N,Kg]^T (fp32 accum)
// BM=BN=128, BK=64, 256 threads, 8 warps of 64x32. cp.async double-buffered.
// ---------------------------------------------------------------------------
#define BM 128
#define BN 128
#define BK 64
#define TILE_BYTES 16384                   // 128 rows x 128 bytes

__device__ __forceinline__ uint32_t smem_u32(const void* p) {
    uint32_t a;
    asm("{ .reg .u64 t; cvta.to.shared.u64 t, %1; cvt.u32.u64 %0, t; }"
        : "=r"(a) : "l"(p));
    return a;
}
#define SWZ(off) ((off) ^ (((off) >> 3) & 0x70))

__device__ __forceinline__ void cp16(uint32_t dst, const void* src) {
    asm volatile("cp.async.cg.shared.global [%0], [%1], 16;"
                 :: "r"(dst), "l"(src) : "memory");
}
__device__ __forceinline__ void ldsm_x4(uint32_t* r, uint32_t addr) {
    asm volatile("ldmatrix.sync.aligned.m8n8.x4.shared.b16 {%0,%1,%2,%3}, [%4];"
                 : "=r"(r[0]), "=r"(r[1]), "=r"(r[2]), "=r"(r[3]) : "r"(addr));
}
__device__ __forceinline__ void mma16816(float* d, const uint32_t* a, const uint32_t* b) {
    asm volatile(
        "mma.sync.aligned.m16n8k16.row.col.f32.bf16.bf16.f32 "
        "{%0,%1,%2,%3}, {%4,%5,%6,%7}, {%8,%9}, {%0,%1,%2,%3};"
        : "+f"(d[0]), "+f"(d[1]), "+f"(d[2]), "+f"(d[3])
        : "r"(a[0]), "r"(a[1]), "r"(a[2]), "r"(a[3]), "r"(b[0]), "r"(b[1]));
}

__global__ __launch_bounds__(256, 2) void gemm_bf16_nt(
    const __nv_bfloat16* __restrict__ A, const __nv_bfloat16* __restrict__ B,
    const float* __restrict__ biasCol, const float* __restrict__ biasRow,
    float* __restrict__ C, int M, int Nn, int Kg)
{
    extern __shared__ __align__(128) char smem[];
    // buffers: A0, B0, A1, B1
    const uint32_t sbase = smem_u32(smem);
    const uint32_t sA[2] = { sbase,                     sbase + 2 * TILE_BYTES };
    const uint32_t sB[2] = { sbase + TILE_BYTES,        sbase + 3 * TILE_BYTES };

    const int tid  = threadIdx.x;
    const int lane = tid & 31;
    const int wid  = tid >> 5;
    const int wm   = wid >> 2;        // 0..1  (64-row bands)
    const int wn   = wid & 3;         // 0..3  (32-col bands)
    const int bm = blockIdx.y * BM;
    const int bn = blockIdx.x * BN;

    const int KT = Kg / BK;

    // per-thread cp.async coordinates: 4 chunks of 16B per operand tile
    const int lrow[4] = { (tid + 0)   >> 3, (tid + 256) >> 3,
                          (tid + 512) >> 3, (tid + 768) >> 3 };
    const int lcb = (tid & 7) * 16;   // byte offset within 128B row

    float acc[4][4][4];
    #pragma unroll
    for (int i = 0; i < 4; i++)
        #pragma unroll
        for (int j = 0; j < 4; j++)
            #pragma unroll
            for (int q = 0; q < 4; q++) acc[i][j][q] = 0.0f;

    auto load_tile = [&](int kt, int buf) {
        const int k0 = kt * BK;       // element offset
        #pragma unroll
        for (int r = 0; r < 4; r++) {
            const int row = lrow[r];
            const uint32_t sw = SWZ((uint32_t)(row * 128 + lcb));
            cp16(sA[buf] + sw, A + (size_t)(bm + row) * Kg + k0 + lcb / 2);
            cp16(sB[buf] + sw, B + (size_t)(bn + row) * Kg + k0 + lcb / 2);
        }
        asm volatile("cp.async.commit_group;" ::: "memory");
    };

    load_tile(0, 0);

    // ldmatrix address components (tile-local, before swizzle)
    const int a_row = wm * 64 + (lane & 15);          // + mi*16
    const int a_kb  = (lane >> 4) * 16;               // + ks*32
    const int b_row = wn * 32 + (lane & 7) + ((lane >> 4) & 1) * 8;  // + ng*16
    const int b_kb  = ((lane >> 3) & 1) * 16;         // + ks*32

    for (int kt = 0; kt < KT; kt++) {
        const int buf = kt & 1;
        if (kt + 1 < KT) {
            load_tile(kt + 1, buf ^ 1);
            asm volatile("cp.async.wait_group 1;" ::: "memory");
        } else {
            asm volatile("cp.async.wait_group 0;" ::: "memory");
        }
        __syncthreads();

        #pragma unroll
        for (int ks = 0; ks < 4; ks++) {
            uint32_t af[4][4], bf[2][4];
            #pragma unroll
            for (int mi = 0; mi < 4; mi++) {
                uint32_t off = (uint32_t)((a_row + mi * 16) * 128 + ks * 32 + a_kb);
                ldsm_x4(af[mi], sA[buf] + SWZ(off));
            }
            #pragma unroll
            for (int ng = 0; ng < 2; ng++) {
                uint32_t off = (uint32_t)((b_row + ng * 16) * 128 + ks * 32 + b_kb);
                ldsm_x4(bf[ng], sB[buf] + SWZ(off));
            }
            #pragma unroll
            for (int mi = 0; mi < 4; mi++)
                #pragma unroll
                for (int ni = 0; ni < 4; ni++)
                    mma16816(acc[mi][ni], af[mi], &bf[ni >> 1][(ni & 1) * 2]);
        }
        __syncthreads();
    }

    // epilogue
    #pragma unroll
    for (int mi = 0; mi < 4; mi++) {
        const int r0 = bm + wm * 64 + mi * 16 + (lane >> 2);
        #pragma unroll
        for (int ni = 0; ni < 4; ni++) {
            const int c = bn + wn * 32 + ni * 8 + (lane & 3) * 2;
            float2 v0 = make_float2(acc[mi][ni][0], acc[mi][ni][1]);
            float2 v1 = make_float2(acc[mi][ni][2], acc[mi][ni][3]);
            if (biasCol) {
                const float2 bc = *(const float2*)(biasCol + c);
                v0.x += bc.x; v0.y += bc.y; v1.x += bc.x; v1.y += bc.y;
            }
            if (biasRow) {
                const float br0 = biasRow[r0];
                const float br1 = biasRow[r0 + 8];
                v0.x += br0; v0.y += br0; v1.x += br1; v1.y += br1;
            }
            *(float2*)(C + (size_t)r0 * Nn + c)       = v0;
            *(float2*)(C + (size_t)(r0 + 8) * Nn + c) = v1;
        }
    }
}

// ---------------------------------------------------------------------------
// Row softmax over 4096 columns.
// ---------------------------------------------------------------------------
__global__ __launch_bounds__(256) void softmax_rows(float* __restrict__ S)
{
    __shared__ float buf[NSEQ];
    __shared__ float red[8];

    const int tid = threadIdx.x;
    const int lane = tid & 31;
    const int warp = tid >> 5;
    float* p = S + (size_t)blockIdx.x * NSEQ;

    float m = -CUDART_INF_F;
    for (int i = tid * 4; i < NSEQ; i += 256 * 4) {
        float4 v = *(const float4*)(p + i);
        *(float4*)&buf[i] = v;
        m = fmaxf(m, fmaxf(fmaxf(v.x, v.y), fmaxf(v.z, v.w)));
    }
    #pragma unroll
    for (int o = 16; o > 0; o >>= 1) m = fmaxf(m, __shfl_xor_sync(0xffffffffu, m, o));
    if (lane == 0) red[warp] = m;
    __syncthreads();
    if (warp == 0) {
        float v = (lane < 8) ? red[lane] : -CUDART_INF_F;
        #pragma unroll
        for (int o = 4; o > 0; o >>= 1) v = fmaxf(v, __shfl_xor_sync(0xffffffffu, v, o));
        if (lane == 0) red[0] = v;
    }
    __syncthreads();
    m = red[0];
    __syncthreads();

    float s = 0.0f;
    for (int i = tid * 4; i < NSEQ; i += 256 * 4) {
        float4 v = *(const float4*)&buf[i];
        v.x = __expf(v.x - m); v.y = __expf(v.y - m);
        v.z = __expf(v.z - m); v.w = __expf(v.w - m);
        *(float4*)&buf[i] = v;
        s += v.x + v.y + v.z + v.w;
    }
    #pragma unroll
    for (int o = 16; o > 0; o >>= 1) s += __shfl_xor_sync(0xffffffffu, s, o);
    if (lane == 0) red[warp] = s;
    __syncthreads();
    if (warp == 0) {
        float v = (lane < 8) ? red[lane] : 0.0f;
        #pragma unroll
        for (int o = 4; o > 0; o >>= 1) v += __shfl_xor_sync(0xffffffffu, v, o);
        if (lane == 0) red[0] = v;
    }
    __syncthreads();
    const float inv = 1.0f / red[0];

    for (int i = tid * 4; i < NSEQ; i += 256 * 4) {
        float4 v = *(const float4*)&buf[i];
        v.x *= inv; v.y *= inv; v.z *= inv; v.w *= inv;
        *(float4*)(p + i) = v;
    }
}

// ---------------------------------------------------------------------------
// Launch
// ---------------------------------------------------------------------------
extern "C" void kernel_launch(void* const* d_in, const int* in_sizes, int n_in,
                              void* d_out, int out_size)
{
    const float* embs = (const float*)d_in[0];
    const float* Wq   = (const float*)d_in[1];
    const float* bq   = (const float*)d_in[2];
    const float* Wk   = (const float*)d_in[3];
    const float* bk   = (const float*)d_in[4];
    const float* Wv   = (const float*)d_in[5];
    const float* bv   = (const float*)d_in[6];
    float* out = (float*)d_out;

    float *Q, *K, *Vt, *S;
    __nv_bfloat16 *ea, *eb, *Wqb, *Wkb, *Wva, *Qa, *Kb, *Sa, *Vtb;
    cudaGetSymbolAddress((void**)&Q,   g_Q);
    cudaGetSymbolAddress((void**)&K,   g_K);
    cudaGetSymbolAddress((void**)&Vt,  g_Vt);
    cudaGetSymbolAddress((void**)&S,   g_S);
    cudaGetSymbolAddress((void**)&ea,  g_ea);
    cudaGetSymbolAddress((void**)&eb,  g_eb);
    cudaGetSymbolAddress((void**)&Wqb, g_Wqb);
    cudaGetSymbolAddress((void**)&Wkb, g_Wkb);
    cudaGetSymbolAddress((void**)&Wva, g_Wva);
    cudaGetSymbolAddress((void**)&Qa,  g_Qa);
    cudaGetSymbolAddress((void**)&Kb,  g_Kb);
    cudaGetSymbolAddress((void**)&Sa,  g_Sa);
    cudaGetSymbolAddress((void**)&Vtb, g_Vtb);

    static int configured = 0;
    const int smem_req = 4 * TILE_BYTES;  // 64 KB
    if (!configured) {
        cudaFuncSetAttribute(gemm_bf16_nt, cudaFuncAttributeMaxDynamicSharedMemorySize, smem_req);
        configured = 1;
    }

    dim3 blk(256);
    auto splits = [&](const float* X, __nv_bfloat16* Y, int M, int Kd, int bside) {
        int total4 = M * Kd / 4;
        split3_kernel<<<(total4 + 255) / 256, blk>>>(X, Y, Kd, total4, bside);
    };

    // conversions of inputs
    splits(embs, ea, NSEQ, DIN, 0);
    splits(embs, eb, NSEQ, DIN, 1);
    splits(Wq,   Wqb, HID, DIN, 1);
    splits(Wk,   Wkb, HID, DIN, 1);
    splits(Wv,   Wva, HID, DIN, 0);

    // projections
    gemm_bf16_nt<<<dim3(HID / BN, NSEQ / BM), blk, smem_req>>>(ea, Wqb, bq, nullptr, Q, NSEQ, HID, 3 * DIN);
    gemm_bf16_nt<<<dim3(HID / BN, NSEQ / BM), blk, smem_req>>>(ea, Wkb, bk, nullptr, K, NSEQ, HID, 3 * DIN);
    gemm_bf16_nt<<<dim3(NSEQ / BN, HID / BM), blk, smem_req>>>(Wva, eb, nullptr, bv, Vt, HID, NSEQ, 3 * DIN);

    splits(Q, Qa, NSEQ, HID, 0);
    splits(K, Kb, NSEQ, HID, 1);
    splits(Vt, Vtb, HID, NSEQ, 1);

    // S = Q @ K^T
    gemm_bf16_nt<<<dim3(NSEQ / BN, NSEQ / BM), blk, smem_req>>>(Qa, Kb, nullptr, nullptr, S, NSEQ, NSEQ, 3 * HID);

    softmax_rows<<<NSEQ, blk>>>(S);

    splits(S, Sa, NSEQ, NSEQ, 0);

    // out = P @ Vt^T
    gemm_bf16_nt<<<dim3(HID / BN, NSEQ / BM), blk, smem_req>>>(Sa, Vtb, nullptr, nullptr, out, NSEQ, HID, 3 * NSEQ);
}

// round 4
// speedup vs baseline: 2.8332x; 1.0689x over previous
#include <cuda_runtime.h>
#include <cuda_bf16.h>
#include <math_constants.h>
#include <cstdint>

#define NSEQ 4096
#define DIN  1024
#define HID  512

// ---------------------------------------------------------------------------
// Device scratch
// ---------------------------------------------------------------------------
__device__ float g_S [(size_t)NSEQ * NSEQ];                 // 64 MB logits

__device__ __nv_bfloat16 g_ea [(size_t)NSEQ * 3 * DIN];    // embs A-form
__device__ __nv_bfloat16 g_eb [(size_t)NSEQ * 3 * DIN];    // embs B-form
__device__ __nv_bfloat16 g_Wqb[(size_t)HID  * 3 * DIN];
__device__ __nv_bfloat16 g_Wkb[(size_t)HID  * 3 * DIN];
__device__ __nv_bfloat16 g_Wva[(size_t)HID  * 3 * DIN];
__device__ __nv_bfloat16 g_Qa [(size_t)NSEQ * 3 * HID];    // Q a-form
__device__ __nv_bfloat16 g_Kb [(size_t)NSEQ * 3 * HID];    // K b-form
__device__ __nv_bfloat16 g_Sa [(size_t)NSEQ * 3 * NSEQ];   // P a-form, 96 MB
__device__ __nv_bfloat16 g_Vtb[(size_t)HID  * 3 * NSEQ];   // Vt b-form

// ---------------------------------------------------------------------------
// Split conversion for raw inputs: X[M,K] fp32 -> Y[M,3K] bf16.
//   A-form: [hi | hi | lo]   B-form: [hi | lo | hi]
// ---------------------------------------------------------------------------
__global__ __launch_bounds__(256) void split3_kernel(
    const float* __restrict__ X, __nv_bfloat16* __restrict__ Y,
    int K, int total4, int bside)
{
    int i = blockIdx.x * blockDim.x + threadIdx.x;
    if (i >= total4) return;
    int e = i * 4;
    int row = e / K;
    int col = e - row * K;

    float4 v = *(const float4*)(X + e);
    __nv_bfloat16 h0 = __float2bfloat16_rn(v.x);
    __nv_bfloat16 h1 = __float2bfloat16_rn(v.y);
    __nv_bfloat16 h2 = __float2bfloat16_rn(v.z);
    __nv_bfloat16 h3 = __float2bfloat16_rn(v.w);
    __nv_bfloat16 l0 = __float2bfloat16_rn(v.x - __bfloat162float(h0));
    __nv_bfloat16 l1 = __float2bfloat16_rn(v.y - __bfloat162float(h1));
    __nv_bfloat16 l2 = __float2bfloat16_rn(v.z - __bfloat162float(h2));
    __nv_bfloat16 l3 = __float2bfloat16_rn(v.w - __bfloat162float(h3));

    ushort4 ph = make_ushort4(__bfloat16_as_ushort(h0), __bfloat16_as_ushort(h1),
                              __bfloat16_as_ushort(h2), __bfloat16_as_ushort(h3));
    ushort4 pl = make_ushort4(__bfloat16_as_ushort(l0), __bfloat16_as_ushort(l1),
                              __bfloat16_as_ushort(l2), __bfloat16_as_ushort(l3));

    size_t base = (size_t)row * (3 * (size_t)K);
    int hi2 = bside ? 2 * K : K;
    int lo1 = bside ? K : 2 * K;
    *(ushort4*)(Y + base + col)       = ph;
    *(ushort4*)(Y + base + hi2 + col) = ph;
    *(ushort4*)(Y + base + lo1 + col) = pl;
}

// ---------------------------------------------------------------------------
// bf16 NT GEMM, mma.sync m16n8k16, 3-buffer cp.async pipeline, one sync/iter.
// C = A[M,Kg] @ B[N,Kg]^T (+bias). Output either fp32 C, or bf16 split form.
// ---------------------------------------------------------------------------
#define BM 128
#define BK 64

__device__ __forceinline__ uint32_t smem_u32(const void* p) {
    uint32_t a;
    asm("{ .reg .u64 t; cvta.to.shared.u64 t, %1; cvt.u32.u64 %0, t; }"
        : "=r"(a) : "l"(p));
    return a;
}
#define SWZ(off) ((off) ^ (((off) >> 3) & 0x70))

__device__ __forceinline__ void cp16(uint32_t dst, const void* src) {
    asm volatile("cp.async.cg.shared.global [%0], [%1], 16;"
                 :: "r"(dst), "l"(src) : "memory");
}
__device__ __forceinline__ void ldsm_x4(uint32_t* r, uint32_t addr) {
    asm volatile("ldmatrix.sync.aligned.m8n8.x4.shared.b16 {%0,%1,%2,%3}, [%4];"
                 : "=r"(r[0]), "=r"(r[1]), "=r"(r[2]), "=r"(r[3]) : "r"(addr));
}
__device__ __forceinline__ void mma16816(float* d, const uint32_t* a, const uint32_t* b) {
    asm volatile(
        "mma.sync.aligned.m16n8k16.row.col.f32.bf16.bf16.f32 "
        "{%0,%1,%2,%3}, {%4,%5,%6,%7}, {%8,%9}, {%0,%1,%2,%3};"
        : "+f"(d[0]), "+f"(d[1]), "+f"(d[2]), "+f"(d[3])
        : "r"(a[0]), "r"(a[1]), "r"(a[2]), "r"(a[3]), "r"(b[0]), "r"(b[1]));
}

template<int BN_T>
__global__ __launch_bounds__(256, 2) void gemm_bf16_nt(
    const __nv_bfloat16* __restrict__ A, const __nv_bfloat16* __restrict__ B,
    const float* __restrict__ biasCol, const float* __restrict__ biasRow,
    float* __restrict__ Cf,                 // fp32 output (or nullptr)
    __nv_bfloat16* __restrict__ Cs,         // split bf16 output (or nullptr)
    int o2, int ol,                         // split: 2nd-hi and lo segment offsets
    int Nn, int Kg)
{
    constexpr int WNC = (BN_T == 128) ? 4 : 2;   // warps along N
    constexpr int MI  = (BN_T == 128) ? 4 : 2;   // 16-row frags per warp
    constexpr int ASZ = BM * 128;                // bytes per A stage
    constexpr int BSZ = BN_T * 128;
    constexpr int STG = ASZ + BSZ;
    constexpr int A_CH = 4;                      // 16B chunks/thread for A
    constexpr int B_CH = BN_T / 32;

    extern __shared__ __align__(128) char smem[];
    const uint32_t sbase = smem_u32(smem);

    const int tid  = threadIdx.x;
    const int lane = tid & 31;
    const int wid  = tid >> 5;
    const int wm   = wid / WNC;
    const int wn   = wid % WNC;
    const int bm = blockIdx.y * BM;
    const int bn = blockIdx.x * BN_T;

    const int KT = Kg / BK;

    float acc[MI][4][4];
    #pragma unroll
    for (int i = 0; i < MI; i++)
        #pragma unroll
        for (int j = 0; j < 4; j++)
            #pragma unroll
            for (int q = 0; q < 4; q++) acc[i][j][q] = 0.0f;

    const int lcb = (tid & 7) * 16;              // byte col within 128B row

    auto load_tile = [&](int kt, int buf) {
        const int k0 = kt * BK;
        const uint32_t sA = sbase + buf * STG;
        const uint32_t sB = sA + ASZ;
        #pragma unroll
        for (int r = 0; r < A_CH; r++) {
            const int row = (tid + r * 256) >> 3;
            cp16(sA + SWZ((uint32_t)(row * 128 + lcb)),
                 A + (size_t)(bm + row) * Kg + k0 + lcb / 2);
        }
        #pragma unroll
        for (int r = 0; r < B_CH; r++) {
            const int row = (tid + r * 256) >> 3;
            cp16(sB + SWZ((uint32_t)(row * 128 + lcb)),
                 B + (size_t)(bn + row) * Kg + k0 + lcb / 2);
        }
        asm volatile("cp.async.commit_group;" ::: "memory");
    };

    load_tile(0, 0);
    load_tile(1, 1);

    const int a_row = wm * (MI * 16) + (lane & 15);
    const int a_kb  = (lane >> 4) * 16;
    const int b_row = wn * 32 + (lane & 7) + ((lane >> 4) & 1) * 8;
    const int b_kb  = ((lane >> 3) & 1) * 16;

    for (int kt = 0; kt < KT; kt++) {
        if (kt < KT - 1) asm volatile("cp.async.wait_group 1;" ::: "memory");
        else             asm volatile("cp.async.wait_group 0;" ::: "memory");
        __syncthreads();

        if (kt + 2 < KT) load_tile(kt + 2, (kt + 2) % 3);

        const uint32_t sA = sbase + (kt % 3) * STG;
        const uint32_t sB = sA + ASZ;

        #pragma unroll
        for (int ks = 0; ks < 4; ks++) {
            uint32_t af[MI][4], bf[2][4];
            #pragma unroll
            for (int mi = 0; mi < MI; mi++) {
                uint32_t off = (uint32_t)((a_row + mi * 16) * 128 + ks * 32 + a_kb);
                ldsm_x4(af[mi], sA + SWZ(off));
            }
            #pragma unroll
            for (int ng = 0; ng < 2; ng++) {
                uint32_t off = (uint32_t)((b_row + ng * 16) * 128 + ks * 32 + b_kb);
                ldsm_x4(bf[ng], sB + SWZ(off));
            }
            #pragma unroll
            for (int mi = 0; mi < MI; mi++)
                #pragma unroll
                for (int ni = 0; ni < 4; ni++)
                    mma16816(acc[mi][ni], af[mi], &bf[ni >> 1][(ni & 1) * 2]);
        }
    }

    // epilogue: thread owns (r0, c..c+1) and (r0+8, c..c+1) per (mi, ni)
    #pragma unroll
    for (int mi = 0; mi < MI; mi++) {
        const int r0 = bm + wm * (MI * 16) + mi * 16 + (lane >> 2);
        #pragma unroll
        for (int ni = 0; ni < 4; ni++) {
            const int c = bn + wn * 32 + ni * 8 + (lane & 3) * 2;
            float2 v0 = make_float2(acc[mi][ni][0], acc[mi][ni][1]);
            float2 v1 = make_float2(acc[mi][ni][2], acc[mi][ni][3]);
            if (biasCol) {
                const float2 bc = *(const float2*)(biasCol + c);
                v0.x += bc.x; v0.y += bc.y; v1.x += bc.x; v1.y += bc.y;
            }
            if (biasRow) {
                const float br0 = biasRow[r0];
                const float br1 = biasRow[r0 + 8];
                v0.x += br0; v0.y += br0; v1.x += br1; v1.y += br1;
            }
            if (Cf) {
                *(float2*)(Cf + (size_t)r0 * Nn + c)       = v0;
                *(float2*)(Cf + (size_t)(r0 + 8) * Nn + c) = v1;
            } else {
                #pragma unroll
                for (int rr = 0; rr < 2; rr++) {
                    const float2 v = rr ? v1 : v0;
                    const size_t base = (size_t)(r0 + rr * 8) * (3 * (size_t)Nn) + c;
                    __nv_bfloat16 hx = __float2bfloat16_rn(v.x);
                    __nv_bfloat16 hy = __float2bfloat16_rn(v.y);
                    __nv_bfloat16 lx = __float2bfloat16_rn(v.x - __bfloat162float(hx));
                    __nv_bfloat16 ly = __float2bfloat16_rn(v.y - __bfloat162float(hy));
                    ushort2 ph = make_ushort2(__bfloat16_as_ushort(hx), __bfloat16_as_ushort(hy));
                    ushort2 pl = make_ushort2(__bfloat16_as_ushort(lx), __bfloat16_as_ushort(ly));
                    *(ushort2*)(Cs + base)      = ph;
                    *(ushort2*)(Cs + base + o2) = ph;
                    *(ushort2*)(Cs + base + ol) = pl;
                }
            }
        }
    }
}

// ---------------------------------------------------------------------------
// Row softmax over 4096 cols; writes P directly in split a-form [hi|hi|lo].
// ---------------------------------------------------------------------------
__global__ __launch_bounds__(256) void softmax_split(
    const float* __restrict__ S, __nv_bfloat16* __restrict__ Sa)
{
    __shared__ float buf[NSEQ];
    __shared__ float red[8];

    const int tid = threadIdx.x;
    const int lane = tid & 31;
    const int warp = tid >> 5;
    const float* p = S + (size_t)blockIdx.x * NSEQ;
    __nv_bfloat16* q = Sa + (size_t)blockIdx.x * (3 * NSEQ);

    float m = -CUDART_INF_F;
    for (int i = tid * 4; i < NSEQ; i += 256 * 4) {
        float4 v = *(const float4*)(p + i);
        *(float4*)&buf[i] = v;
        m = fmaxf(m, fmaxf(fmaxf(v.x, v.y), fmaxf(v.z, v.w)));
    }
    #pragma unroll
    for (int o = 16; o > 0; o >>= 1) m = fmaxf(m, __shfl_xor_sync(0xffffffffu, m, o));
    if (lane == 0) red[warp] = m;
    __syncthreads();
    if (warp == 0) {
        float v = (lane < 8) ? red[lane] : -CUDART_INF_F;
        #pragma unroll
        for (int o = 4; o > 0; o >>= 1) v = fmaxf(v, __shfl_xor_sync(0xffffffffu, v, o));
        if (lane == 0) red[0] = v;
    }
    __syncthreads();
    m = red[0];
    __syncthreads();

    float s = 0.0f;
    for (int i = tid * 4; i < NSEQ; i += 256 * 4) {
        float4 v = *(const float4*)&buf[i];
        v.x = __expf(v.x - m); v.y = __expf(v.y - m);
        v.z = __expf(v.z - m); v.w = __expf(v.w - m);
        *(float4*)&buf[i] = v;
        s += v.x + v.y + v.z + v.w;
    }
    #pragma unroll
    for (int o = 16; o > 0; o >>= 1) s += __shfl_xor_sync(0xffffffffu, s, o);
    if (lane == 0) red[warp] = s;
    __syncthreads();
    if (warp == 0) {
        float v = (lane < 8) ? red[lane] : 0.0f;
        #pragma unroll
        for (int o = 4; o > 0; o >>= 1) v += __shfl_xor_sync(0xffffffffu, v, o);
        if (lane == 0) red[0] = v;
    }
    __syncthreads();
    const float inv = 1.0f / red[0];

    for (int i = tid * 4; i < NSEQ; i += 256 * 4) {
        float4 v = *(const float4*)&buf[i];
        v.x *= inv; v.y *= inv; v.z *= inv; v.w *= inv;
        __nv_bfloat16 h0 = __float2bfloat16_rn(v.x);
        __nv_bfloat16 h1 = __float2bfloat16_rn(v.y);
        __nv_bfloat16 h2 = __float2bfloat16_rn(v.z);
        __nv_bfloat16 h3 = __float2bfloat16_rn(v.w);
        ushort4 ph = make_ushort4(__bfloat16_as_ushort(h0), __bfloat16_as_ushort(h1),
                                  __bfloat16_as_ushort(h2), __bfloat16_as_ushort(h3));
        __nv_bfloat16 l0 = __float2bfloat16_rn(v.x - __bfloat162float(h0));
        __nv_bfloat16 l1 = __float2bfloat16_rn(v.y - __bfloat162float(h1));
        __nv_bfloat16 l2 = __float2bfloat16_rn(v.z - __bfloat162float(h2));
        __nv_bfloat16 l3 = __float2bfloat16_rn(v.w - __bfloat162float(h3));
        ushort4 pl = make_ushort4(__bfloat16_as_ushort(l0), __bfloat16_as_ushort(l1),
                                  __bfloat16_as_ushort(l2), __bfloat16_as_ushort(l3));
        *(ushort4*)(q + i)            = ph;
        *(ushort4*)(q + NSEQ + i)     = ph;
        *(ushort4*)(q + 2 * NSEQ + i) = pl;
    }
}

// ---------------------------------------------------------------------------
// Launch
// ---------------------------------------------------------------------------
extern "C" void kernel_launch(void* const* d_in, const int* in_sizes, int n_in,
                              void* d_out, int out_size)
{
    const float* embs = (const float*)d_in[0];
    const float* Wq   = (const float*)d_in[1];
    const float* bq   = (const float*)d_in[2];
    const float* Wk   = (const float*)d_in[3];
    const float* bk   = (const float*)d_in[4];
    const float* Wv   = (const float*)d_in[5];
    const float* bv   = (const float*)d_in[6];
    float* out = (float*)d_out;

    float *S;
    __nv_bfloat16 *ea, *eb, *Wqb, *Wkb, *Wva, *Qa, *Kb, *Sa, *Vtb;
    cudaGetSymbolAddress((void**)&S,   g_S);
    cudaGetSymbolAddress((void**)&ea,  g_ea);
    cudaGetSymbolAddress((void**)&eb,  g_eb);
    cudaGetSymbolAddress((void**)&Wqb, g_Wqb);
    cudaGetSymbolAddress((void**)&Wkb, g_Wkb);
    cudaGetSymbolAddress((void**)&Wva, g_Wva);
    cudaGetSymbolAddress((void**)&Qa,  g_Qa);
    cudaGetSymbolAddress((void**)&Kb,  g_Kb);
    cudaGetSymbolAddress((void**)&Sa,  g_Sa);
    cudaGetSymbolAddress((void**)&Vtb, g_Vtb);

    const int smem128 = 3 * (128 + 128) * 128;   // 96 KB
    const int smem64  = 3 * (128 + 64) * 128;    // 72 KB
    cudaFuncSetAttribute(gemm_bf16_nt<128>, cudaFuncAttributeMaxDynamicSharedMemorySize, smem128);
    cudaFuncSetAttribute(gemm_bf16_nt<64>,  cudaFuncAttributeMaxDynamicSharedMemorySize, smem64);

    dim3 blk(256);
    auto splits = [&](const float* X, __nv_bfloat16* Y, int M, int Kd, int bside) {
        int total4 = M * Kd / 4;
        split3_kernel<<<(total4 + 255) / 256, blk>>>(X, Y, Kd, total4, bside);
    };

    // input conversions (5 launches)
    splits(embs, ea,  NSEQ, DIN, 0);
    splits(embs, eb,  NSEQ, DIN, 1);
    splits(Wq,   Wqb, HID,  DIN, 1);
    splits(Wk,   Wkb, HID,  DIN, 1);
    splits(Wv,   Wva, HID,  DIN, 0);

    // Q projection -> Qa (a-form: hi@0, hi@HID, lo@2*HID)
    gemm_bf16_nt<64><<<dim3(HID / 64, NSEQ / BM), blk, smem64>>>(
        ea, Wqb, bq, nullptr, nullptr, Qa, HID, 2 * HID, HID, 3 * DIN);
    // K projection -> Kb (b-form: hi@0, lo@HID, hi@2*HID)
    gemm_bf16_nt<64><<<dim3(HID / 64, NSEQ / BM), blk, smem64>>>(
        ea, Wkb, bk, nullptr, nullptr, Kb, 2 * HID, HID, HID, 3 * DIN);
    // Vt projection -> Vtb (b-form over NSEQ)
    gemm_bf16_nt<64><<<dim3(NSEQ / 64, HID / BM), blk, smem64>>>(
        Wva, eb, nullptr, bv, nullptr, Vtb, 2 * NSEQ, NSEQ, NSEQ, 3 * DIN);

    // S = Q @ K^T (fp32)
    gemm_bf16_nt<128><<<dim3(NSEQ / 128, NSEQ / BM), blk, smem128>>>(
        Qa, Kb, nullptr, nullptr, S, nullptr, 0, 0, NSEQ, 3 * HID);

    // softmax + split -> Sa
    softmax_split<<<NSEQ, blk>>>(S, Sa);

    // out = P @ Vt^T (fp32)
    gemm_bf16_nt<64><<<dim3(HID / 64, NSEQ / BM), blk, smem64>>>(
        Sa, Vtb, nullptr, nullptr, out, nullptr, 0, 0, HID, 3 * NSEQ);
}

// round 6
// speedup vs baseline: 3.0610x; 1.0804x over previous
#include <cuda_runtime.h>
#include <cuda_bf16.h>
#include <math_constants.h>
#include <cstdint>

#define NSEQ 4096
#define DIN  1024
#define HID  512

// ---------------------------------------------------------------------------
// Device scratch
// ---------------------------------------------------------------------------
__device__ float g_S [(size_t)NSEQ * NSEQ];                 // 64 MB logits

__device__ __nv_bfloat16 g_ea [(size_t)NSEQ * 3 * DIN];    // embs A-form
__device__ __nv_bfloat16 g_eb [(size_t)NSEQ * 3 * DIN];    // embs B-form
__device__ __nv_bfloat16 g_Wqb[(size_t)HID  * 3 * DIN];
__device__ __nv_bfloat16 g_Wkb[(size_t)HID  * 3 * DIN];
__device__ __nv_bfloat16 g_Wva[(size_t)HID  * 3 * DIN];
__device__ __nv_bfloat16 g_Qa [(size_t)NSEQ * 3 * HID];    // Q a-form
__device__ __nv_bfloat16 g_Kb [(size_t)NSEQ * 3 * HID];    // K b-form
__device__ __nv_bfloat16 g_Sa [(size_t)NSEQ * 3 * NSEQ];   // P a-form, 96 MB
__device__ __nv_bfloat16 g_Vtb[(size_t)HID  * 3 * NSEQ];   // Vt b-form

// ---------------------------------------------------------------------------
// Split conversion for raw inputs: X[M,K] fp32 -> Y[M,3K] bf16.
//   A-form: [hi | hi | lo]   B-form: [hi | lo | hi]
// ---------------------------------------------------------------------------
__global__ __launch_bounds__(256) void split3_kernel(
    const float* __restrict__ X, __nv_bfloat16* __restrict__ Y,
    int K, int total4, int bside)
{
    int i = blockIdx.x * blockDim.x + threadIdx.x;
    if (i >= total4) return;
    int e = i * 4;
    int row = e / K;
    int col = e - row * K;

    float4 v = *(const float4*)(X + e);
    __nv_bfloat16 h0 = __float2bfloat16_rn(v.x);
    __nv_bfloat16 h1 = __float2bfloat16_rn(v.y);
    __nv_bfloat16 h2 = __float2bfloat16_rn(v.z);
    __nv_bfloat16 h3 = __float2bfloat16_rn(v.w);
    __nv_bfloat16 l0 = __float2bfloat16_rn(v.x - __bfloat162float(h0));
    __nv_bfloat16 l1 = __float2bfloat16_rn(v.y - __bfloat162float(h1));
    __nv_bfloat16 l2 = __float2bfloat16_rn(v.z - __bfloat162float(h2));
    __nv_bfloat16 l3 = __float2bfloat16_rn(v.w - __bfloat162float(h3));

    ushort4 ph = make_ushort4(__bfloat16_as_ushort(h0), __bfloat16_as_ushort(h1),
                              __bfloat16_as_ushort(h2), __bfloat16_as_ushort(h3));
    ushort4 pl = make_ushort4(__bfloat16_as_ushort(l0), __bfloat16_as_ushort(l1),
                              __bfloat16_as_ushort(l2), __bfloat16_as_ushort(l3));

    size_t base = (size_t)row * (3 * (size_t)K);
    int hi2 = bside ? 2 * K : K;
    int lo1 = bside ? K : 2 * K;
    *(ushort4*)(Y + base + col)       = ph;
    *(ushort4*)(Y + base + hi2 + col) = ph;
    *(ushort4*)(Y + base + lo1 + col) = pl;
}

// ---------------------------------------------------------------------------
// bf16 NT GEMM, mma.sync m16n8k16. 128 threads, 2x2 warps, warp tile
// 64 x (BN_T/2). 3-stage cp.async pipeline, one __syncthreads per K tile.
// Optional second operand set (B2/bias2/Cs2) selected when bn >= nsplit,
// used to fuse the Q and K projections into one launch.
// ---------------------------------------------------------------------------
#define BM 128
#define BK 64

__device__ __forceinline__ uint32_t smem_u32(const void* p) {
    uint32_t a;
    asm("{ .reg .u64 t; cvta.to.shared.u64 t, %1; cvt.u32.u64 %0, t; }"
        : "=r"(a) : "l"(p));
    return a;
}
#define SWZ(off) ((off) ^ (((off) >> 3) & 0x70))

__device__ __forceinline__ void cp16(uint32_t dst, const void* src) {
    asm volatile("cp.async.cg.shared.global [%0], [%1], 16;"
                 :: "r"(dst), "l"(src) : "memory");
}
__device__ __forceinline__ void ldsm_x4(uint32_t* r, uint32_t addr) {
    asm volatile("ldmatrix.sync.aligned.m8n8.x4.shared.b16 {%0,%1,%2,%3}, [%4];"
                 : "=r"(r[0]), "=r"(r[1]), "=r"(r[2]), "=r"(r[3]) : "r"(addr));
}
__device__ __forceinline__ void mma16816(float* d, const uint32_t* a, const uint32_t* b) {
    asm volatile(
        "mma.sync.aligned.m16n8k16.row.col.f32.bf16.bf16.f32 "
        "{%0,%1,%2,%3}, {%4,%5,%6,%7}, {%8,%9}, {%0,%1,%2,%3};"
        : "+f"(d[0]), "+f"(d[1]), "+f"(d[2]), "+f"(d[3])
        : "r"(a[0]), "r"(a[1]), "r"(a[2]), "r"(a[3]), "r"(b[0]), "r"(b[1]));
}

template<int BN_T>
__global__ __launch_bounds__(128, 2) void gemm_bf16_nt(
    const __nv_bfloat16* __restrict__ A,
    const __nv_bfloat16* __restrict__ B,
    const __nv_bfloat16* __restrict__ B2,
    const float* __restrict__ biasCol,
    const float* __restrict__ biasCol2,
    const float* __restrict__ biasRow,
    float* __restrict__ Cf,                 // fp32 output (or nullptr)
    __nv_bfloat16* __restrict__ Cs,         // split bf16 output (or nullptr)
    __nv_bfloat16* __restrict__ Cs2,
    int o2, int ol, int o2b, int olb,
    int nsplit,                             // 0 = no fusion
    int Nn, int Kg)
{
    constexpr int NI  = BN_T / 16;               // n8 frags per warp (8 or 4)
    constexpr int NG  = NI / 2;                  // ldmatrix x4 groups for B
    constexpr int ASZ = BM * 128;                // bytes per A stage (16 KB)
    constexpr int BSZ = BN_T * 128;
    constexpr int STG = ASZ + BSZ;
    constexpr int A_CH = 8;                      // 16B chunks/thread for A
    constexpr int B_CH = BN_T / 16;              // 8 or 4

    extern __shared__ __align__(128) char smem[];
    const uint32_t sbase = smem_u32(smem);

    const int tid  = threadIdx.x;
    const int lane = tid & 31;
    const int wid  = tid >> 5;
    const int wm   = wid >> 1;                   // 0..1
    const int wn   = wid & 1;                    // 0..1
    const int bm = blockIdx.y * BM;
    int bn = blockIdx.x * BN_T;

    // fused-QK half selection
    if (nsplit && bn >= nsplit) {
        B = B2; biasCol = biasCol2; Cs = Cs2; o2 = o2b; ol = olb;
        bn -= nsplit;
    }

    const int KT = Kg / BK;

    float acc[4][NI][4];
    #pragma unroll
    for (int i = 0; i < 4; i++)
        #pragma unroll
        for (int j = 0; j < NI; j++)
            #pragma unroll
            for (int q = 0; q < 4; q++) acc[i][j][q] = 0.0f;

    const int lcb = (tid & 7) * 16;              // byte col within 128B row

    auto load_tile = [&](int kt, int buf) {
        const int k0 = kt * BK;
        const uint32_t sA = sbase + buf * STG;
        const uint32_t sB = sA + ASZ;
        #pragma unroll
        for (int r = 0; r < A_CH; r++) {
            const int row = (tid + r * 128) >> 3;
            cp16(sA + SWZ((uint32_t)(row * 128 + lcb)),
                 A + (size_t)(bm + row) * Kg + k0 + lcb / 2);
        }
        #pragma unroll
        for (int r = 0; r < B_CH; r++) {
            const int row = (tid + r * 128) >> 3;
            cp16(sB + SWZ((uint32_t)(row * 128 + lcb)),
                 B + (size_t)(bn + row) * Kg + k0 + lcb / 2);
        }
        asm volatile("cp.async.commit_group;" ::: "memory");
    };

    load_tile(0, 0);
    load_tile(1, 1);

    const int a_row = wm * 64 + (lane & 15);
    const int a_kb  = (lane >> 4) * 16;
    const int b_row = wn * (BN_T / 2) + (lane & 7) + ((lane >> 4) & 1) * 8;
    const int b_kb  = ((lane >> 3) & 1) * 16;

    for (int kt = 0; kt < KT; kt++) {
        if (kt < KT - 1) asm volatile("cp.async.wait_group 1;" ::: "memory");
        else             asm volatile("cp.async.wait_group 0;" ::: "memory");
        __syncthreads();

        if (kt + 2 < KT) load_tile(kt + 2, (kt + 2) % 3);

        const uint32_t sA = sbase + (kt % 3) * STG;
        const uint32_t sB = sA + ASZ;

        #pragma unroll
        for (int ks = 0; ks < 4; ks++) {
            uint32_t af[4][4], bf[NG][4];
            #pragma unroll
            for (int mi = 0; mi < 4; mi++) {
                uint32_t off = (uint32_t)((a_row + mi * 16) * 128 + ks * 32 + a_kb);
                ldsm_x4(af[mi], sA + SWZ(off));
            }
            #pragma unroll
            for (int ng = 0; ng < NG; ng++) {
                uint32_t off = (uint32_t)((b_row + ng * 16) * 128 + ks * 32 + b_kb);
                ldsm_x4(bf[ng], sB + SWZ(off));
            }
            #pragma unroll
            for (int mi = 0; mi < 4; mi++)
                #pragma unroll
                for (int ni = 0; ni < NI; ni++)
                    mma16816(acc[mi][ni], af[mi], &bf[ni >> 1][(ni & 1) * 2]);
        }
    }

    // epilogue
    #pragma unroll
    for (int mi = 0; mi < 4; mi++) {
        const int r0 = bm + wm * 64 + mi * 16 + (lane >> 2);
        #pragma unroll
        for (int ni = 0; ni < NI; ni++) {
            const int c = bn + wn * (BN_T / 2) + ni * 8 + (lane & 3) * 2;
            float2 v0 = make_float2(acc[mi][ni][0], acc[mi][ni][1]);
            float2 v1 = make_float2(acc[mi][ni][2], acc[mi][ni][3]);
            if (biasCol) {
                const float2 bc = *(const float2*)(biasCol + c);
                v0.x += bc.x; v0.y += bc.y; v1.x += bc.x; v1.y += bc.y;
            }
            if (biasRow) {
                const float br0 = biasRow[r0];
                const float br1 = biasRow[r0 + 8];
                v0.x += br0; v0.y += br0; v1.x += br1; v1.y += br1;
            }
            if (Cf) {
                *(float2*)(Cf + (size_t)r0 * Nn + c)       = v0;
                *(float2*)(Cf + (size_t)(r0 + 8) * Nn + c) = v1;
            } else {
                #pragma unroll
                for (int rr = 0; rr < 2; rr++) {
                    const float2 v = rr ? v1 : v0;
                    const size_t base = (size_t)(r0 + rr * 8) * (3 * (size_t)Nn) + c;
                    __nv_bfloat16 hx = __float2bfloat16_rn(v.x);
                    __nv_bfloat16 hy = __float2bfloat16_rn(v.y);
                    __nv_bfloat16 lx = __float2bfloat16_rn(v.x - __bfloat162float(hx));
                    __nv_bfloat16 ly = __float2bfloat16_rn(v.y - __bfloat162float(hy));
                    ushort2 ph = make_ushort2(__bfloat16_as_ushort(hx), __bfloat16_as_ushort(hy));
                    ushort2 pl = make_ushort2(__bfloat16_as_ushort(lx), __bfloat16_as_ushort(ly));
                    *(ushort2*)(Cs + base)      = ph;
                    *(ushort2*)(Cs + base + o2) = ph;
                    *(ushort2*)(Cs + base + ol) = pl;
                }
            }
        }
    }
}

// ---------------------------------------------------------------------------
// Row softmax over 4096 cols; writes P directly in split a-form [hi|hi|lo].
// ---------------------------------------------------------------------------
__global__ __launch_bounds__(256) void softmax_split(
    const float* __restrict__ S, __nv_bfloat16* __restrict__ Sa)
{
    __shared__ float buf[NSEQ];
    __shared__ float red[8];

    const int tid = threadIdx.x;
    const int lane = tid & 31;
    const int warp = tid >> 5;
    const float* p = S + (size_t)blockIdx.x * NSEQ;
    __nv_bfloat16* q = Sa + (size_t)blockIdx.x * (3 * NSEQ);

    float m = -CUDART_INF_F;
    for (int i = tid * 4; i < NSEQ; i += 256 * 4) {
        float4 v = *(const float4*)(p + i);
        *(float4*)&buf[i] = v;
        m = fmaxf(m, fmaxf(fmaxf(v.x, v.y), fmaxf(v.z, v.w)));
    }
    #pragma unroll
    for (int o = 16; o > 0; o >>= 1) m = fmaxf(m, __shfl_xor_sync(0xffffffffu, m, o));
    if (lane == 0) red[warp] = m;
    __syncthreads();
    if (warp == 0) {
        float v = (lane < 8) ? red[lane] : -CUDART_INF_F;
        #pragma unroll
        for (int o = 4; o > 0; o >>= 1) v = fmaxf(v, __shfl_xor_sync(0xffffffffu, v, o));
        if (lane == 0) red[0] = v;
    }
    __syncthreads();
    m = red[0];
    __syncthreads();

    float s = 0.0f;
    for (int i = tid * 4; i < NSEQ; i += 256 * 4) {
        float4 v = *(const float4*)&buf[i];
        v.x = __expf(v.x - m); v.y = __expf(v.y - m);
        v.z = __expf(v.z - m); v.w = __expf(v.w - m);
        *(float4*)&buf[i] = v;
        s += v.x + v.y + v.z + v.w;
    }
    #pragma unroll
    for (int o = 16; o > 0; o >>= 1) s += __shfl_xor_sync(0xffffffffu, s, o);
    if (lane == 0) red[warp] = s;
    __syncthreads();
    if (warp == 0) {
        float v = (lane < 8) ? red[lane] : 0.0f;
        #pragma unroll
        for (int o = 4; o > 0; o >>= 1) v += __shfl_xor_sync(0xffffffffu, v, o);
        if (lane == 0) red[0] = v;
    }
    __syncthreads();
    const float inv = 1.0f / red[0];

    for (int i = tid * 4; i < NSEQ; i += 256 * 4) {
        float4 v = *(const float4*)&buf[i];
        v.x *= inv; v.y *= inv; v.z *= inv; v.w *= inv;
        __nv_bfloat16 h0 = __float2bfloat16_rn(v.x);
        __nv_bfloat16 h1 = __float2bfloat16_rn(v.y);
        __nv_bfloat16 h2 = __float2bfloat16_rn(v.z);
        __nv_bfloat16 h3 = __float2bfloat16_rn(v.w);
        ushort4 ph = make_ushort4(__bfloat16_as_ushort(h0), __bfloat16_as_ushort(h1),
                                  __bfloat16_as_ushort(h2), __bfloat16_as_ushort(h3));
        __nv_bfloat16 l0 = __float2bfloat16_rn(v.x - __bfloat162float(h0));
        __nv_bfloat16 l1 = __float2bfloat16_rn(v.y - __bfloat162float(h1));
        __nv_bfloat16 l2 = __float2bfloat16_rn(v.z - __bfloat162float(h2));
        __nv_bfloat16 l3 = __float2bfloat16_rn(v.w - __bfloat162float(h3));
        ushort4 pl = make_ushort4(__bfloat16_as_ushort(l0), __bfloat16_as_ushort(l1),
                                  __bfloat16_as_ushort(l2), __bfloat16_as_ushort(l3));
        *(ushort4*)(q + i)            = ph;
        *(ushort4*)(q + NSEQ + i)     = ph;
        *(ushort4*)(q + 2 * NSEQ + i) = pl;
    }
}

// ---------------------------------------------------------------------------
// Launch
// ---------------------------------------------------------------------------
extern "C" void kernel_launch(void* const* d_in, const int* in_sizes, int n_in,
                              void* d_out, int out_size)
{
    const float* embs = (const float*)d_in[0];
    const float* Wq   = (const float*)d_in[1];
    const float* bq   = (const float*)d_in[2];
    const float* Wk   = (const float*)d_in[3];
    const float* bk   = (const float*)d_in[4];
    const float* Wv   = (const float*)d_in[5];
    const float* bv   = (const float*)d_in[6];
    float* out = (float*)d_out;

    float *S;
    __nv_bfloat16 *ea, *eb, *Wqb, *Wkb, *Wva, *Qa, *Kb, *Sa, *Vtb;
    cudaGetSymbolAddress((void**)&S,   g_S);
    cudaGetSymbolAddress((void**)&ea,  g_ea);
    cudaGetSymbolAddress((void**)&eb,  g_eb);
    cudaGetSymbolAddress((void**)&Wqb, g_Wqb);
    cudaGetSymbolAddress((void**)&Wkb, g_Wkb);
    cudaGetSymbolAddress((void**)&Wva, g_Wva);
    cudaGetSymbolAddress((void**)&Qa,  g_Qa);
    cudaGetSymbolAddress((void**)&Kb,  g_Kb);
    cudaGetSymbolAddress((void**)&Sa,  g_Sa);
    cudaGetSymbolAddress((void**)&Vtb, g_Vtb);

    const int smem128 = 3 * (128 + 128) * 128;   // 96 KB
    const int smem64  = 3 * (128 + 64) * 128;    // 72 KB
    cudaFuncSetAttribute(gemm_bf16_nt<128>, cudaFuncAttributeMaxDynamicSharedMemorySize, smem128);
    cudaFuncSetAttribute(gemm_bf16_nt<64>,  cudaFuncAttributeMaxDynamicSharedMemorySize, smem64);

    dim3 blk(128);
    dim3 blk256(256);
    auto splits = [&](const float* X, __nv_bfloat16* Y, int M, int Kd, int bside) {
        int total4 = M * Kd / 4;
        split3_kernel<<<(total4 + 255) / 256, blk256>>>(X, Y, Kd, total4, bside);
    };

    // input conversions (5 launches)
    splits(embs, ea,  NSEQ, DIN, 0);
    splits(embs, eb,  NSEQ, DIN, 1);
    splits(Wq,   Wqb, HID,  DIN, 1);
    splits(Wk,   Wkb, HID,  DIN, 1);
    splits(Wv,   Wva, HID,  DIN, 0);

    // fused Q+K projection: N domain [0,512)->Q (a-form), [512,1024)->K (b-form)
    gemm_bf16_nt<128><<<dim3(2 * HID / 128, NSEQ / BM), blk, smem128>>>(
        ea, Wqb, Wkb, bq, bk, nullptr, nullptr,
        Qa, Kb, HID, 2 * HID, 2 * HID, HID, HID, HID, 3 * DIN);

    // Vt projection -> Vtb (b-form over NSEQ): A=Wva [512 x 3072], B=eb
    gemm_bf16_nt<64><<<dim3(NSEQ / 64, HID / BM), blk, smem64>>>(
        Wva, eb, nullptr, nullptr, nullptr, bv, nullptr,
        Vtb, nullptr, 2 * NSEQ, NSEQ, 0, 0, 0, NSEQ, 3 * DIN);

    // S = Q @ K^T (fp32)
    gemm_bf16_nt<128><<<dim3(NSEQ / 128, NSEQ / BM), blk, smem128>>>(
        Qa, Kb, nullptr, nullptr, nullptr, nullptr, S,
        nullptr, nullptr, 0, 0, 0, 0, 0, NSEQ, 3 * HID);

    // softmax + split -> Sa
    softmax_split<<<NSEQ, blk256>>>(S, Sa);

    // out = P @ Vt^T (fp32)
    gemm_bf16_nt<64><<<dim3(HID / 64, NSEQ / BM), blk, smem64>>>(
        Sa, Vtb, nullptr, nullptr, nullptr, nullptr, out,
        nullptr, nullptr, 0, 0, 0, 0, 0, HID, 3 * NSEQ);
}

// round 7
// speedup vs baseline: 5.0069x; 1.6357x over previous
#include <cuda_runtime.h>
#include <cuda_bf16.h>
#include <cuda_fp16.h>
#include <math_constants.h>
#include <cstdint>

#define NSEQ 4096
#define DIN  1024
#define HID  512

typedef unsigned short u16;

// ---------------------------------------------------------------------------
// Device scratch
// ---------------------------------------------------------------------------
__device__ float g_S [(size_t)NSEQ * NSEQ];                // 64 MB logits

__device__ __nv_bfloat16 g_ea [(size_t)NSEQ * 3 * DIN];    // embs bf16 a3-form
__device__ __nv_bfloat16 g_Wqb[(size_t)HID  * 3 * DIN];    // Wq  bf16 b3-form
__device__ __nv_bfloat16 g_Wkb[(size_t)HID  * 3 * DIN];    // Wk  bf16 b3-form
__device__ u16 g_eh [(size_t)NSEQ * DIN];                  // embs fp16
__device__ u16 g_Wvh[(size_t)HID  * DIN];                  // Wv   fp16
__device__ u16 g_Qa [(size_t)NSEQ * 2 * HID];              // [Qh | Ql] fp16
__device__ u16 g_Kb [(size_t)NSEQ * 2 * HID];              // [Kh | Kh] fp16
__device__ u16 g_Ph [(size_t)NSEQ * NSEQ];                 // P fp16, 32 MB
__device__ u16 g_Vth[(size_t)HID  * NSEQ];                 // Vt fp16

// ---------------------------------------------------------------------------
// Input conversions
// ---------------------------------------------------------------------------
__global__ __launch_bounds__(256) void split3_kernel(
    const float* __restrict__ X, __nv_bfloat16* __restrict__ Y,
    int K, int total4, int bside)
{
    int i = blockIdx.x * blockDim.x + threadIdx.x;
    if (i >= total4) return;
    int e = i * 4;
    int row = e / K;
    int col = e - row * K;

    float4 v = *(const float4*)(X + e);
    __nv_bfloat16 h0 = __float2bfloat16_rn(v.x);
    __nv_bfloat16 h1 = __float2bfloat16_rn(v.y);
    __nv_bfloat16 h2 = __float2bfloat16_rn(v.z);
    __nv_bfloat16 h3 = __float2bfloat16_rn(v.w);
    __nv_bfloat16 l0 = __float2bfloat16_rn(v.x - __bfloat162float(h0));
    __nv_bfloat16 l1 = __float2bfloat16_rn(v.y - __bfloat162float(h1));
    __nv_bfloat16 l2 = __float2bfloat16_rn(v.z - __bfloat162float(h2));
    __nv_bfloat16 l3 = __float2bfloat16_rn(v.w - __bfloat162float(h3));

    ushort4 ph = make_ushort4(__bfloat16_as_ushort(h0), __bfloat16_as_ushort(h1),
                              __bfloat16_as_ushort(h2), __bfloat16_as_ushort(h3));
    ushort4 pl = make_ushort4(__bfloat16_as_ushort(l0), __bfloat16_as_ushort(l1),
                              __bfloat16_as_ushort(l2), __bfloat16_as_ushort(l3));

    size_t base = (size_t)row * (3 * (size_t)K);
    int hi2 = bside ? 2 * K : K;
    int lo1 = bside ? K : 2 * K;
    *(ushort4*)(Y + base + col)       = ph;
    *(ushort4*)(Y + base + hi2 + col) = ph;
    *(ushort4*)(Y + base + lo1 + col) = pl;
}

__global__ __launch_bounds__(256) void cvt_half_kernel(
    const float* __restrict__ X, u16* __restrict__ Y, int total4)
{
    int i = blockIdx.x * blockDim.x + threadIdx.x;
    if (i >= total4) return;
    float4 v = *(const float4*)(X + i * 4);
    ushort4 h;
    h.x = __half_as_ushort(__float2half_rn(v.x));
    h.y = __half_as_ushort(__float2half_rn(v.y));
    h.z = __half_as_ushort(__float2half_rn(v.z));
    h.w = __half_as_ushort(__float2half_rn(v.w));
    *(ushort4*)(Y + i * 4) = h;
}

// ---------------------------------------------------------------------------
// 16-bit NT GEMM, mma.sync m16n8k16 (bf16 or fp16). 128 threads, 2x2 warps,
// warp tile 64 x (BN_T/2). 3-stage cp.async pipeline, one sync per K tile.
// Output modes: fp32 (Cf), fp16 plain (Ch), fp16 2-seg split (Cs: hi@0,
// hi-or-lo @ +o2 per dupHi). Optional fused second half (B2/.../Cs2) when
// bn >= nsplit.
// ---------------------------------------------------------------------------
#define BM 128
#define BK 64

__device__ __forceinline__ uint32_t smem_u32(const void* p) {
    uint32_t a;
    asm("{ .reg .u64 t; cvta.to.shared.u64 t, %1; cvt.u32.u64 %0, t; }"
        : "=r"(a) : "l"(p));
    return a;
}
#define SWZ(off) ((off) ^ (((off) >> 3) & 0x70))

__device__ __forceinline__ void cp16(uint32_t dst, const void* src) {
    asm volatile("cp.async.cg.shared.global [%0], [%1], 16;"
                 :: "r"(dst), "l"(src) : "memory");
}
__device__ __forceinline__ void ldsm_x4(uint32_t* r, uint32_t addr) {
    asm volatile("ldmatrix.sync.aligned.m8n8.x4.shared.b16 {%0,%1,%2,%3}, [%4];"
                 : "=r"(r[0]), "=r"(r[1]), "=r"(r[2]), "=r"(r[3]) : "r"(addr));
}
template<bool FP16>
__device__ __forceinline__ void mma16816(float* d, const uint32_t* a, const uint32_t* b);
template<>
__device__ __forceinline__ void mma16816<false>(float* d, const uint32_t* a, const uint32_t* b) {
    asm volatile(
        "mma.sync.aligned.m16n8k16.row.col.f32.bf16.bf16.f32 "
        "{%0,%1,%2,%3}, {%4,%5,%6,%7}, {%8,%9}, {%0,%1,%2,%3};"
        : "+f"(d[0]), "+f"(d[1]), "+f"(d[2]), "+f"(d[3])
        : "r"(a[0]), "r"(a[1]), "r"(a[2]), "r"(a[3]), "r"(b[0]), "r"(b[1]));
}
template<>
__device__ __forceinline__ void mma16816<true>(float* d, const uint32_t* a, const uint32_t* b) {
    asm volatile(
        "mma.sync.aligned.m16n8k16.row.col.f32.f16.f16.f32 "
        "{%0,%1,%2,%3}, {%4,%5,%6,%7}, {%8,%9}, {%0,%1,%2,%3};"
        : "+f"(d[0]), "+f"(d[1]), "+f"(d[2]), "+f"(d[3])
        : "r"(a[0]), "r"(a[1]), "r"(a[2]), "r"(a[3]), "r"(b[0]), "r"(b[1]));
}

template<int BN_T, bool FP16>
__global__ __launch_bounds__(128, 2) void gemm_nt(
    const u16* __restrict__ A,
    const u16* __restrict__ B,
    const u16* __restrict__ B2,
    const float* __restrict__ biasCol,
    const float* __restrict__ biasCol2,
    const float* __restrict__ biasRow,
    float* __restrict__ Cf,                 // fp32 out
    u16*   __restrict__ Ch,                 // fp16 plain out
    u16*   __restrict__ Cs,                 // fp16 2-seg split out
    u16*   __restrict__ Cs2,
    int o2, int dupHi, int dupHi2,
    int nsplit, int Nn, int Kg)
{
    constexpr int NI  = BN_T / 16;
    constexpr int NG  = NI / 2;
    constexpr int ASZ = BM * 128;
    constexpr int BSZ = BN_T * 128;
    constexpr int STG = ASZ + BSZ;
    constexpr int A_CH = 8;
    constexpr int B_CH = BN_T / 16;

    extern __shared__ __align__(128) char smem[];
    const uint32_t sbase = smem_u32(smem);

    const int tid  = threadIdx.x;
    const int lane = tid & 31;
    const int wid  = tid >> 5;
    const int wm   = wid >> 1;
    const int wn   = wid & 1;
    const int bm = blockIdx.y * BM;
    int bn = blockIdx.x * BN_T;
    int dup = dupHi;

    if (nsplit && bn >= nsplit) {
        B = B2; biasCol = biasCol2; Cs = Cs2; dup = dupHi2;
        bn -= nsplit;
    }

    const int KT = Kg / BK;

    float acc[4][NI][4];
    #pragma unroll
    for (int i = 0; i < 4; i++)
        #pragma unroll
        for (int j = 0; j < NI; j++)
            #pragma unroll
            for (int q = 0; q < 4; q++) acc[i][j][q] = 0.0f;

    const int lcb = (tid & 7) * 16;

    auto load_tile = [&](int kt, int buf) {
        const int k0 = kt * BK;
        const uint32_t sA = sbase + buf * STG;
        const uint32_t sB = sA + ASZ;
        #pragma unroll
        for (int r = 0; r < A_CH; r++) {
            const int row = (tid + r * 128) >> 3;
            cp16(sA + SWZ((uint32_t)(row * 128 + lcb)),
                 A + (size_t)(bm + row) * Kg + k0 + lcb / 2);
        }
        #pragma unroll
        for (int r = 0; r < B_CH; r++) {
            const int row = (tid + r * 128) >> 3;
            cp16(sB + SWZ((uint32_t)(row * 128 + lcb)),
                 B + (size_t)(bn + row) * Kg + k0 + lcb / 2);
        }
        asm volatile("cp.async.commit_group;" ::: "memory");
    };

    load_tile(0, 0);
    load_tile(1, 1);

    const int a_row = wm * 64 + (lane & 15);
    const int a_kb  = (lane >> 4) * 16;
    const int b_row = wn * (BN_T / 2) + (lane & 7) + ((lane >> 4) & 1) * 8;
    const int b_kb  = ((lane >> 3) & 1) * 16;

    for (int kt = 0; kt < KT; kt++) {
        if (kt < KT - 1) asm volatile("cp.async.wait_group 1;" ::: "memory");
        else             asm volatile("cp.async.wait_group 0;" ::: "memory");
        __syncthreads();

        if (kt + 2 < KT) load_tile(kt + 2, (kt + 2) % 3);

        const uint32_t sA = sbase + (kt % 3) * STG;
        const uint32_t sB = sA + ASZ;

        #pragma unroll
        for (int ks = 0; ks < 4; ks++) {
            uint32_t af[4][4], bf[NG][4];
            #pragma unroll
            for (int mi = 0; mi < 4; mi++) {
                uint32_t off = (uint32_t)((a_row + mi * 16) * 128 + ks * 32 + a_kb);
                ldsm_x4(af[mi], sA + SWZ(off));
            }
            #pragma unroll
            for (int ng = 0; ng < NG; ng++) {
                uint32_t off = (uint32_t)((b_row + ng * 16) * 128 + ks * 32 + b_kb);
                ldsm_x4(bf[ng], sB + SWZ(off));
            }
            #pragma unroll
            for (int mi = 0; mi < 4; mi++)
                #pragma unroll
                for (int ni = 0; ni < NI; ni++)
                    mma16816<FP16>(acc[mi][ni], af[mi], &bf[ni >> 1][(ni & 1) * 2]);
        }
    }

    // epilogue
    #pragma unroll
    for (int mi = 0; mi < 4; mi++) {
        const int r0 = bm + wm * 64 + mi * 16 + (lane >> 2);
        #pragma unroll
        for (int ni = 0; ni < NI; ni++) {
            const int c = bn + wn * (BN_T / 2) + ni * 8 + (lane & 3) * 2;
            float2 v0 = make_float2(acc[mi][ni][0], acc[mi][ni][1]);
            float2 v1 = make_float2(acc[mi][ni][2], acc[mi][ni][3]);
            if (biasCol) {
                const float2 bc = *(const float2*)(biasCol + c);
                v0.x += bc.x; v0.y += bc.y; v1.x += bc.x; v1.y += bc.y;
            }
            if (biasRow) {
                const float br0 = biasRow[r0];
                const float br1 = biasRow[r0 + 8];
                v0.x += br0; v0.y += br0; v1.x += br1; v1.y += br1;
            }
            if (Cf) {
                *(float2*)(Cf + (size_t)r0 * Nn + c)       = v0;
                *(float2*)(Cf + (size_t)(r0 + 8) * Nn + c) = v1;
            } else if (Ch) {
                #pragma unroll
                for (int rr = 0; rr < 2; rr++) {
                    const float2 v = rr ? v1 : v0;
                    ushort2 h;
                    h.x = __half_as_ushort(__float2half_rn(v.x));
                    h.y = __half_as_ushort(__float2half_rn(v.y));
                    *(ushort2*)(Ch + (size_t)(r0 + rr * 8) * Nn + c) = h;
                }
            } else {
                #pragma unroll
                for (int rr = 0; rr < 2; rr++) {
                    const float2 v = rr ? v1 : v0;
                    const size_t base = (size_t)(r0 + rr * 8) * (2 * (size_t)Nn) + c;
                    __half hx = __float2half_rn(v.x);
                    __half hy = __float2half_rn(v.y);
                    ushort2 ph = make_ushort2(__half_as_ushort(hx), __half_as_ushort(hy));
                    ushort2 p2;
                    if (dup) {
                        p2 = ph;
                    } else {
                        __half lx = __float2half_rn(v.x - __half2float(hx));
                        __half ly = __float2half_rn(v.y - __half2float(hy));
                        p2 = make_ushort2(__half_as_ushort(lx), __half_as_ushort(ly));
                    }
                    *(ushort2*)(Cs + base)      = ph;
                    *(ushort2*)(Cs + base + o2) = p2;
                }
            }
        }
    }
}

// ---------------------------------------------------------------------------
// Row softmax over 4096 cols -> fp16 P.
// ---------------------------------------------------------------------------
__global__ __launch_bounds__(256) void softmax_half(
    const float* __restrict__ S, u16* __restrict__ P)
{
    __shared__ float buf[NSEQ];
    __shared__ float red[8];

    const int tid = threadIdx.x;
    const int lane = tid & 31;
    const int warp = tid >> 5;
    const float* p = S + (size_t)blockIdx.x * NSEQ;
    u16* q = P + (size_t)blockIdx.x * NSEQ;

    float m = -CUDART_INF_F;
    for (int i = tid * 4; i < NSEQ; i += 256 * 4) {
        float4 v = *(const float4*)(p + i);
        *(float4*)&buf[i] = v;
        m = fmaxf(m, fmaxf(fmaxf(v.x, v.y), fmaxf(v.z, v.w)));
    }
    #pragma unroll
    for (int o = 16; o > 0; o >>= 1) m = fmaxf(m, __shfl_xor_sync(0xffffffffu, m, o));
    if (lane == 0) red[warp] = m;
    __syncthreads();
    if (warp == 0) {
        float v = (lane < 8) ? red[lane] : -CUDART_INF_F;
        #pragma unroll
        for (int o = 4; o > 0; o >>= 1) v = fmaxf(v, __shfl_xor_sync(0xffffffffu, v, o));
        if (lane == 0) red[0] = v;
    }
    __syncthreads();
    m = red[0];
    __syncthreads();

    float s = 0.0f;
    for (int i = tid * 4; i < NSEQ; i += 256 * 4) {
        float4 v = *(const float4*)&buf[i];
        v.x = __expf(v.x - m); v.y = __expf(v.y - m);
        v.z = __expf(v.z - m); v.w = __expf(v.w - m);
        *(float4*)&buf[i] = v;
        s += v.x + v.y + v.z + v.w;
    }
    #pragma unroll
    for (int o = 16; o > 0; o >>= 1) s += __shfl_xor_sync(0xffffffffu, s, o);
    if (lane == 0) red[warp] = s;
    __syncthreads();
    if (warp == 0) {
        float v = (lane < 8) ? red[lane] : 0.0f;
        #pragma unroll
        for (int o = 4; o > 0; o >>= 1) v += __shfl_xor_sync(0xffffffffu, v, o);
        if (lane == 0) red[0] = v;
    }
    __syncthreads();
    const float inv = 1.0f / red[0];

    for (int i = tid * 4; i < NSEQ; i += 256 * 4) {
        float4 v = *(const float4*)&buf[i];
        ushort4 h;
        h.x = __half_as_ushort(__float2half_rn(v.x * inv));
        h.y = __half_as_ushort(__float2half_rn(v.y * inv));
        h.z = __half_as_ushort(__float2half_rn(v.z * inv));
        h.w = __half_as_ushort(__float2half_rn(v.w * inv));
        *(ushort4*)(q + i) = h;
    }
}

// ---------------------------------------------------------------------------
// Launch
// ---------------------------------------------------------------------------
extern "C" void kernel_launch(void* const* d_in, const int* in_sizes, int n_in,
                              void* d_out, int out_size)
{
    const float* embs = (const float*)d_in[0];
    const float* Wq   = (const float*)d_in[1];
    const float* bq   = (const float*)d_in[2];
    const float* Wk   = (const float*)d_in[3];
    const float* bk   = (const float*)d_in[4];
    const float* Wv   = (const float*)d_in[5];
    const float* bv   = (const float*)d_in[6];
    float* out = (float*)d_out;

    float *S;
    __nv_bfloat16 *ea, *Wqb, *Wkb;
    u16 *eh, *Wvh, *Qa, *Kb, *Ph, *Vth;
    cudaGetSymbolAddress((void**)&S,   g_S);
    cudaGetSymbolAddress((void**)&ea,  g_ea);
    cudaGetSymbolAddress((void**)&Wqb, g_Wqb);
    cudaGetSymbolAddress((void**)&Wkb, g_Wkb);
    cudaGetSymbolAddress((void**)&eh,  g_eh);
    cudaGetSymbolAddress((void**)&Wvh, g_Wvh);
    cudaGetSymbolAddress((void**)&Qa,  g_Qa);
    cudaGetSymbolAddress((void**)&Kb,  g_Kb);
    cudaGetSymbolAddress((void**)&Ph,  g_Ph);
    cudaGetSymbolAddress((void**)&Vth, g_Vth);

    const int smem128 = 3 * (128 + 128) * 128;   // 96 KB
    const int smem64  = 3 * (128 + 64) * 128;    // 72 KB
    cudaFuncSetAttribute((const void*)gemm_nt<128, false>, cudaFuncAttributeMaxDynamicSharedMemorySize, smem128);
    cudaFuncSetAttribute((const void*)gemm_nt<128, true>,  cudaFuncAttributeMaxDynamicSharedMemorySize, smem128);
    cudaFuncSetAttribute((const void*)gemm_nt<64, true>,   cudaFuncAttributeMaxDynamicSharedMemorySize, smem64);

    dim3 blk(128);
    dim3 blk256(256);

    // input conversions
    {
        int t4 = NSEQ * DIN / 4;
        split3_kernel<<<(t4 + 255) / 256, blk256>>>(embs, ea, DIN, t4, 0);
        cvt_half_kernel<<<(t4 + 255) / 256, blk256>>>(embs, eh, t4);
        int w4 = HID * DIN / 4;
        split3_kernel<<<(w4 + 255) / 256, blk256>>>(Wq, Wqb, DIN, w4, 1);
        split3_kernel<<<(w4 + 255) / 256, blk256>>>(Wk, Wkb, DIN, w4, 1);
        cvt_half_kernel<<<(w4 + 255) / 256, blk256>>>(Wv, Wvh, w4);
    }

    // fused Q+K projection (bf16 3-term in, fp16 2-seg out):
    //   N [0,512) -> Qa = [Qh | Ql],  N [512,1024) -> Kb = [Kh | Kh]
    gemm_nt<128, false><<<dim3(2 * HID / 128, NSEQ / BM), blk, smem128>>>(
        (const u16*)ea, (const u16*)Wqb, (const u16*)Wkb,
        bq, bk, nullptr,
        nullptr, nullptr, Qa, Kb,
        HID, 0, 1, HID, HID, 3 * DIN);

    // Vt projection (fp16 1-term): Vt[h][n] = Wv[h,:] . embs[n,:] + bv[h]
    gemm_nt<64, true><<<dim3(NSEQ / 64, HID / BM), blk, smem64>>>(
        Wvh, eh, nullptr,
        nullptr, nullptr, bv,
        nullptr, Vth, nullptr, nullptr,
        0, 0, 0, 0, NSEQ, DIN);

    // S = Q @ K^T (fp16 2-term, Kg = 1024)
    gemm_nt<128, true><<<dim3(NSEQ / 128, NSEQ / BM), blk, smem128>>>(
        Qa, Kb, nullptr,
        nullptr, nullptr, nullptr,
        S, nullptr, nullptr, nullptr,
        0, 0, 0, 0, NSEQ, 2 * HID);

    // softmax -> fp16 P
    softmax_half<<<NSEQ, blk256>>>(S, Ph);

    // out = P @ Vt^T (fp16 1-term, Kg = 4096)
    gemm_nt<64, true><<<dim3(HID / 64, NSEQ / BM), blk, smem64>>>(
        Ph, Vth, nullptr,
        nullptr, nullptr, nullptr,
        out, nullptr, nullptr, nullptr,
        0, 0, 0, 0, HID, NSEQ);
}